// round 1
// baseline (speedup 1.0000x reference)
#include <cuda_runtime.h>
#include <math.h>

#define N_PTS 32768

// ---------------- scratch (device globals; no allocations allowed) ----------
__device__ float g_bufA[N_PTS * 256];
__device__ float g_bufB[N_PTS * 256];
__device__ float g_w0[288 * 256];
__device__ float g_w1[2304 * 256];
__device__ float g_w2[2304 * 256];
__device__ float g_w3[2304];

// ---------------- B-spline helpers ------------------------------------------
// knots: arange(-3, 9) * 0.4 + (-1.0), fp32
__device__ __forceinline__ constexpr float kn(int i) {
    return (float)(i - 3) * 0.4f + (-1.0f);
}

// Cubic B-spline bases (8 values) via the reference's Cox-de Boor recurrence.
__device__ __forceinline__ void bspline8(float t, float* bb) {
    float b[11];
#pragma unroll
    for (int i = 0; i < 11; i++)
        b[i] = (t >= kn(i) && t < kn(i + 1)) ? 1.0f : 0.0f;
#pragma unroll
    for (int k = 1; k <= 3; k++) {
#pragma unroll
        for (int i = 0; i < 11 - k; i++) {
            float invdl = 1.0f / (kn(i + k) - kn(i));
            float invdr = 1.0f / (kn(i + k + 1) - kn(i + 1));
            float l = (t - kn(i)) * invdl;
            float r = (kn(i + k + 1) - t) * invdr;
            b[i] = l * b[i] + r * b[i + 1];
        }
    }
#pragma unroll
    for (int i = 0; i < 8; i++) bb[i] = b[i];
}

__device__ __forceinline__ float silu_f(float v) {
    return v * (1.0f / (1.0f + __expf(-v)));
}

// ---------------- weight prep: Wl[k*O + o], k = f*9 + j ---------------------
// j==0 -> bw[o,f]; j in 1..8 -> sw[o,f,j-1] * ss[o,f]
__global__ void prep_w(const float* __restrict__ bw, const float* __restrict__ sw,
                       const float* __restrict__ ss, float* __restrict__ Wl,
                       int F, int O) {
    int idx = blockIdx.x * blockDim.x + threadIdx.x;
    int K = F * 9;
    if (idx >= K * O) return;
    int k = idx / O, o = idx - k * O;
    int f = k / 9, j = k - f * 9;
    float v;
    if (j == 0) v = bw[o * F + f];
    else        v = sw[(o * F + f) * 8 + (j - 1)] * ss[o * F + f];
    Wl[idx] = v;
}

// ---------------- positional encoding ---------------------------------------
// h0[n, j] = sin(x[n]*freq[j]), h0[n, 16+j] = cos(...). Accurate range
// reduction in double so result matches JAX fp32 sin/cos regardless of
// fast-math flags (enc magnitude up to ~1e5).
__global__ void encode_kernel(const float* __restrict__ x,
                              const float* __restrict__ freq,
                              float* __restrict__ h0) {
    int idx = blockIdx.x * blockDim.x + threadIdx.x;   // N*16 threads
    if (idx >= N_PTS * 16) return;
    int n = idx >> 4, j = idx & 15;
    float enc = x[n] * freq[j];                         // same fp32 rounding as ref
    double ed = (double)enc;
    double q = rint(ed * 0.15915494309189535);          // 1/(2*pi)
    double rd = fma(-q, 6.283185307179586, ed);         // r in [-pi, pi]
    float r = (float)rd;
    float s, c;
    __sincosf(r, &s, &c);                               // accurate on [-pi, pi]
    h0[n * 32 + j] = s;
    h0[n * 32 + 16 + j] = c;
}

// ---------------- fused KAN layer: out(N,256) = A(N,9F) @ W(9F,256) ---------
// TM=64 rows x TN=256 cols per block, 256 threads, 8x8 register microtiles.
// A (silu + 8 spline bases) is computed on the fly into smem, K-major.
template <int F>
__global__ void __launch_bounds__(256, 2)
kan_layer(const float* __restrict__ hin, const float* __restrict__ W,
          float* __restrict__ hout) {
    constexpr int TM = 64, TN = 256, FC = 4, KC = FC * 9;  // KC = 36
    __shared__ float A_s[KC * TM];   //  9.2 KB, layout [k][row]
    __shared__ float W_s[KC * TN];   // 36.9 KB, layout [k][col]

    const int tid = threadIdx.x;
    const int tx = tid & 31;         // col group: cols tx*8 .. tx*8+7
    const int ty = tid >> 5;         // row group: rows ty*8 .. ty*8+7
    const int row0 = blockIdx.x * TM;
    const int ar = tid & 63;         // A-producer: row
    const int af = tid >> 6;         // A-producer: local feature 0..3

    float acc[8][8];
#pragma unroll
    for (int r = 0; r < 8; r++)
#pragma unroll
        for (int c = 0; c < 8; c++) acc[r][c] = 0.0f;

    for (int f0 = 0; f0 < F; f0 += FC) {
        __syncthreads();
        // -- produce A tile: one (row, feature) pair per thread
        {
            float t = hin[(row0 + ar) * F + f0 + af];
            float bb[8];
            bspline8(t, bb);
            A_s[(af * 9 + 0) * TM + ar] = silu_f(t);
#pragma unroll
            for (int jj = 0; jj < 8; jj++)
                A_s[(af * 9 + 1 + jj) * TM + ar] = bb[jj];
        }
        // -- stage W tile (contiguous KC*TN block), 9 float4 per thread
        {
            const float4* src = reinterpret_cast<const float4*>(W + f0 * 9 * TN);
            float4* dst = reinterpret_cast<float4*>(W_s);
#pragma unroll
            for (int i = 0; i < 9; i++) dst[tid + i * 256] = src[tid + i * 256];
        }
        __syncthreads();
        // -- 8x8 microtile FMA over the K chunk
#pragma unroll 4
        for (int k = 0; k < KC; k++) {
            float a[8], w[8];
            *reinterpret_cast<float4*>(a)     = *reinterpret_cast<const float4*>(&A_s[k * TM + ty * 8]);
            *reinterpret_cast<float4*>(a + 4) = *reinterpret_cast<const float4*>(&A_s[k * TM + ty * 8 + 4]);
            *reinterpret_cast<float4*>(w)     = *reinterpret_cast<const float4*>(&W_s[k * TN + tx * 8]);
            *reinterpret_cast<float4*>(w + 4) = *reinterpret_cast<const float4*>(&W_s[k * TN + tx * 8 + 4]);
#pragma unroll
            for (int r = 0; r < 8; r++)
#pragma unroll
                for (int c = 0; c < 8; c++) acc[r][c] += a[r] * w[c];
        }
    }
    // -- epilogue: coalesced float4 stores
#pragma unroll
    for (int r = 0; r < 8; r++) {
        float4 v0 = make_float4(acc[r][0], acc[r][1], acc[r][2], acc[r][3]);
        float4 v1 = make_float4(acc[r][4], acc[r][5], acc[r][6], acc[r][7]);
        float4* o = reinterpret_cast<float4*>(hout + (row0 + ty * 8 + r) * TN + tx * 8);
        o[0] = v0;
        o[1] = v1;
    }
}

// ---------------- last layer: O = 1 ------------------------------------------
__global__ void kan_last(const float* __restrict__ hin,
                         const float* __restrict__ W,   // 2304 floats
                         float* __restrict__ out) {
    __shared__ float Ws[2304];
    int tid = threadIdx.x;
#pragma unroll
    for (int i = tid; i < 2304; i += 256) Ws[i] = W[i];
    __syncthreads();
    int warp = tid >> 5, lane = tid & 31;
    int n = blockIdx.x * 8 + warp;
    float sum = 0.0f;
#pragma unroll
    for (int ff = 0; ff < 8; ff++) {
        int f = ff * 32 + lane;
        float t = hin[n * 256 + f];
        float bb[8];
        bspline8(t, bb);
        float sl = silu_f(t) * Ws[f * 9];
#pragma unroll
        for (int j = 0; j < 8; j++) sl += bb[j] * Ws[f * 9 + 1 + j];
        sum += sl;
    }
#pragma unroll
    for (int off = 16; off; off >>= 1)
        sum += __shfl_xor_sync(0xffffffffu, sum, off);
    if (lane == 0) out[n] = sum;
}

// ---------------- launch ------------------------------------------------------
extern "C" void kernel_launch(void* const* d_in, const int* in_sizes, int n_in,
                              void* d_out, int out_size) {
    const float* x    = (const float*)d_in[0];
    const float* freq = (const float*)d_in[1];
    const float* bw0  = (const float*)d_in[2];
    const float* sw0  = (const float*)d_in[3];
    const float* ss0  = (const float*)d_in[4];
    const float* bw1  = (const float*)d_in[5];
    const float* sw1  = (const float*)d_in[6];
    const float* ss1  = (const float*)d_in[7];
    const float* bw2  = (const float*)d_in[8];
    const float* sw2  = (const float*)d_in[9];
    const float* ss2  = (const float*)d_in[10];
    const float* bw3  = (const float*)d_in[11];
    const float* sw3  = (const float*)d_in[12];
    const float* ss3  = (const float*)d_in[13];
    float* out = (float*)d_out;

    float *bufA, *bufB, *w0, *w1, *w2, *w3;
    cudaGetSymbolAddress((void**)&bufA, g_bufA);
    cudaGetSymbolAddress((void**)&bufB, g_bufB);
    cudaGetSymbolAddress((void**)&w0, g_w0);
    cudaGetSymbolAddress((void**)&w1, g_w1);
    cudaGetSymbolAddress((void**)&w2, g_w2);
    cudaGetSymbolAddress((void**)&w3, g_w3);

    // weight prep (cheap, fully independent of the activation chain)
    prep_w<<<(288 * 256 + 255) / 256, 256>>>(bw0, sw0, ss0, w0, 32, 256);
    prep_w<<<(2304 * 256 + 255) / 256, 256>>>(bw1, sw1, ss1, w1, 256, 256);
    prep_w<<<(2304 * 256 + 255) / 256, 256>>>(bw2, sw2, ss2, w2, 256, 256);
    prep_w<<<(2304 + 255) / 256, 256>>>(bw3, sw3, ss3, w3, 256, 1);

    encode_kernel<<<(N_PTS * 16) / 256, 256>>>(x, freq, bufA);

    kan_layer<32><<<N_PTS / 64, 256>>>(bufA, w0, bufB);
    kan_layer<256><<<N_PTS / 64, 256>>>(bufB, w1, bufA);
    kan_layer<256><<<N_PTS / 64, 256>>>(bufA, w2, bufB);
    kan_last<<<N_PTS / 8, 256>>>(bufB, w3, out);
}